// round 16
// baseline (speedup 1.0000x reference)
#include <cuda_runtime.h>
#include <cuda_fp16.h>
#include <cuda_bf16.h>

#define NB      4
#define TT      32
#define DW      300
#define HD      128     // per-direction hidden
#define G3      384     // 3*HD
#define HID     256     // DIM_HIDDEN
#define GDIM    64
#define DESCL   16
#define NNODES  20000
#define NEDGES  320000
#define NCLASS  2000
#define VDESC   30000
#define DP      68      // padded desc row in smem
#define TGRID   148
#define CHUNK   136     // ceil(NNODES/TGRID)

// launch-1 block layout
#define GXB     64
#define HISTB   140
#define CONVB   80
#define NCONV   (VDESC * GDIM / 8)   // 240000 uint4 outputs

// launch-3 block layout
#define BUCKB   150
#define NFB3    ((NNODES + 2) / 3)   // 6667 nodefeat blocks (3 nodes each)

// launch-4: gts, 16 nodes per block, 1 warp per node (round-11 proven optimum)
#define GTSB    (NNODES / 16)        // 1250

// ---------------- scratch (device globals; zero-init at load) ---------------
// g_counts, g_qg start zero and are re-zeroed by the tail of each call.
__device__ float g_gxa[2 * NB * TT * G3];
__device__ float g_gxb[2 * NB * TT * G3];
__device__ float g_qemb[NB * HID];
__device__ float g_qg[NB * GDIM];             // accum: maintained zero
__device__ __half g_desch[(size_t)VDESC * GDIM];      // fp16 desc table
__device__ __half g_nfh[(size_t)NNODES * NB * GDIM];  // node feats (fp16)
__device__ __half g_nf2h[(size_t)NNODES * NB * GDIM]; // post-RGCN (fp16)
__device__ int   g_counts[NNODES];            // maintained zero
__device__ int   g_offsets[NNODES + 1];
__device__ int   g_cursor[NNODES];
__device__ int   g_ssrc[NEDGES];
__device__ float g_sw[NEDGES];
__device__ float g_s2[NB * NNODES];
__device__ float g_pmax[TGRID * NB];
__device__ float g_psum[TGRID * NB];
__device__ float g_nagg[NB * GDIM];
__device__ float g_hidden[NB * 1024];
__device__ volatile unsigned g_barcnt;
__device__ volatile unsigned g_barsense;

__device__ __forceinline__ float sigmoidf_(float x) { return 1.f / (1.f + __expf(-x)); }

// =====================================================================
// Launch 1 (384 thr): gx[0,64) | hist | desc->fp16   (all low-register)
// =====================================================================
__global__ void __launch_bounds__(384) k_front(
    const int* __restrict__ q, const float* __restrict__ emb_word,
    const float* __restrict__ Wx_f, const float* __restrict__ bx_f,
    const float* __restrict__ Wx_b, const float* __restrict__ bx_b,
    const int* __restrict__ edst, const float* __restrict__ emb_desc) {
    int bid = blockIdx.x, tid = threadIdx.x;
    if (bid < GXB) {
        int half = bid >> 5, dir = (bid >> 4) & 1, b = (bid >> 2) & 3, tq = bid & 3;
        const float* Wx = dir ? Wx_b : Wx_f;
        const float* bx = dir ? bx_b : bx_f;
        int k0 = half * 150;
        __shared__ float xs[8 * 150];
        for (int i = tid; i < 8 * 150; i += 384) {
            int t = i / 150, k = i % 150;
            int tok = q[b * TT + tq * 8 + t];
            xs[i] = emb_word[(long)tok * DW + k0 + k];
        }
        __syncthreads();
        float acc[8];
        float bj = half ? 0.f : bx[tid];
#pragma unroll
        for (int t = 0; t < 8; t++) acc[t] = bj;
        for (int k = 0; k < 150; k++) {
            float w = Wx[(long)(k0 + k) * G3 + tid];
#pragma unroll
            for (int t = 0; t < 8; t++) acc[t] += xs[t * 150 + k] * w;
        }
        float* dst = half ? g_gxb : g_gxa;
#pragma unroll
        for (int t = 0; t < 8; t++)
            dst[((dir * NB + b) * TT + tq * 8 + t) * G3 + tid] = acc[t];
    } else if (bid < GXB + HISTB) {
        for (int i = (bid - GXB) * 384 + tid; i < NEDGES; i += HISTB * 384)
            atomicAdd(&g_counts[edst[i]], 1);
    } else {
        const float4* src = (const float4*)emb_desc;
        for (int j = (bid - GXB - HISTB) * 384 + tid; j < NCONV; j += CONVB * 384) {
            float4 a = src[2 * j], c = src[2 * j + 1];
            union { uint4 u; __half2 h[4]; } pk;
            pk.h[0] = __float22half2_rn(make_float2(a.x, a.y));
            pk.h[1] = __float22half2_rn(make_float2(a.z, a.w));
            pk.h[2] = __float22half2_rn(make_float2(c.x, c.y));
            pk.h[3] = __float22half2_rn(make_float2(c.z, c.w));
            ((uint4*)g_desch)[j] = pk.u;
        }
    }
#if __CUDA_ARCH__ >= 900
    cudaTriggerProgrammaticLaunchCompletion();
#endif
}

// =====================================================================
// Launch 2 (9 blocks x 384): GRU[0..7] (Wh register-resident + q_g GEMV)
//                            + scan[8] (runs concurrent; its time hides)
// PDL secondary: Wh preload happens BEFORE the dependency sync.
// =====================================================================
__global__ void __launch_bounds__(384, 1) k_gru(
    const float* __restrict__ Wh_f, const float* __restrict__ bh_f,
    const float* __restrict__ Wh_b, const float* __restrict__ bh_b,
    const int* __restrict__ q, const float* __restrict__ W_hg) {
    int tid = threadIdx.x;
    if (blockIdx.x < 8) {
        __shared__ float4 h4s[HD / 4];
        __shared__ float ghs[G3];
        int rb = blockIdx.x;
        int dir = rb >> 2, b = rb & 3;
        const float* Wh = dir ? Wh_b : Wh_f;
        const float* bh = dir ? bh_b : bh_f;
        float w[HD];
#pragma unroll
        for (int k = 0; k < HD; k++) w[k] = Wh[k * G3 + tid];
        float bhj = bh[tid];
        float hreg = 0.f;
        if (tid < HD) ((float*)h4s)[tid] = 0.f;
#if __CUDA_ARCH__ >= 900
        cudaGridDependencySynchronize();   // wait for gx before recurrence
#endif
        __syncthreads();
        for (int step = 0; step < TT; step++) {
            int t = dir ? (TT - 1 - step) : step;
            const float* gA = &g_gxa[((dir * NB + b) * TT + t) * G3];
            const float* gB = &g_gxb[((dir * NB + b) * TT + t) * G3];
            float gx0 = 0.f, gx1 = 0.f, gx2 = 0.f;
            int mtok = 0;
            if (tid < HD) {
                gx0 = gA[tid] + gB[tid];
                gx1 = gA[tid + HD] + gB[tid + HD];
                gx2 = gA[tid + 2 * HD] + gB[tid + 2 * HD];
                mtok = q[b * TT + t];
            }
            float acc = bhj;
#pragma unroll
            for (int k4 = 0; k4 < HD / 4; k4++) {
                float4 h4 = h4s[k4];
                acc += h4.x * w[4 * k4] + h4.y * w[4 * k4 + 1]
                     + h4.z * w[4 * k4 + 2] + h4.w * w[4 * k4 + 3];
            }
            ghs[tid] = acc;
            __syncthreads();
            if (tid < HD) {
                float r  = sigmoidf_(gx0 + acc);
                float z  = sigmoidf_(gx1 + ghs[tid + HD]);
                float nn = tanhf(gx2 + r * ghs[tid + 2 * HD]);
                float hnew = (1.f - z) * nn + z * hreg;
                hreg = mtok ? hnew : hreg;
                ((float*)h4s)[tid] = hreg;
            }
            __syncthreads();
        }
        if (tid < HD) g_qemb[b * HID + dir * HD + tid] = hreg;
        if (tid < GDIM) {
            const float* hh = (const float*)h4s;
            float acc = 0.f;
#pragma unroll 8
            for (int k = 0; k < HD; k++)
                acc += hh[k] * W_hg[(dir * HD + k) * GDIM + tid];
            atomicAdd(&g_qg[b * GDIM + tid], acc);
        }
    } else {
        // ---- exclusive scan of g_counts -> g_offsets, g_cursor (384 thr) ----
#if __CUDA_ARCH__ >= 900
        cudaGridDependencySynchronize();   // counts must be final
#endif
        __shared__ int wsum[12];
        __shared__ int carry_s;
        int lane = tid & 31, wid = tid >> 5;
        if (tid == 0) carry_s = 0;
        __syncthreads();
        int nchunk = (NNODES + 383) / 384;
        for (int c = 0; c < nchunk; c++) {
            int i = c * 384 + tid;
            int v = (i < NNODES) ? g_counts[i] : 0;
            int x = v;
#pragma unroll
            for (int o = 1; o < 32; o <<= 1) { int y = __shfl_up_sync(~0u, x, o); if (lane >= o) x += y; }
            if (lane == 31) wsum[wid] = x;
            __syncthreads();
            if (wid == 0) {
                int s = (lane < 12) ? wsum[lane] : 0;
#pragma unroll
                for (int o = 1; o < 32; o <<= 1) { int y = __shfl_up_sync(~0u, s, o); if (lane >= o) s += y; }
                if (lane < 12) wsum[lane] = s;
            }
            __syncthreads();
            int incl = x + (wid > 0 ? wsum[wid - 1] : 0);
            int total = wsum[11];
            int base = carry_s;
            if (i < NNODES) { int e = base + incl - v; g_offsets[i] = e; g_cursor[i] = e; }
            __syncthreads();
            if (tid == 0) carry_s = base + total;
            __syncthreads();
        }
        if (tid == 0) g_offsets[NNODES] = carry_s;
    }
#if __CUDA_ARCH__ >= 900
    cudaTriggerProgrammaticLaunchCompletion();
#endif
}

// =====================================================================
// Launch 3 (384 thr): bucket[0,150) | nodefeat (3 nodes/block)
// PDL secondary: nodefeat desc gather (safe 2 launches back) precedes sync.
// =====================================================================
__global__ void __launch_bounds__(384) k_mid(
    const int* __restrict__ node_descs, const float* __restrict__ b_hg,
    const int* __restrict__ esrc, const int* __restrict__ edst,
    const int* __restrict__ etype, const float* __restrict__ w_comp) {
    int blk = blockIdx.x, tid = threadIdx.x;
    if (blk < BUCKB) {
#if __CUDA_ARCH__ >= 900
        cudaGridDependencySynchronize();   // needs g_cursor from scan
#endif
        for (int i = blk * 384 + tid; i < NEDGES; i += BUCKB * 384) {
            int d = edst[i];
            int pos = atomicAdd(&g_cursor[d], 1);
            g_ssrc[pos] = esrc[i];
            g_sw[pos]   = w_comp[etype[i]];
        }
    } else {
        __shared__ float ds[3][DESCL * DP];
        __shared__ float qgs[NB * GDIM];
        __shared__ float sc[3][NB * DESCL];
        __shared__ float at[3][NB * DESCL];
        int sub = tid >> 7, t2 = tid & 127;      // 3 nodes, 128 threads each
        int n = (blk - BUCKB) * 3 + sub;
        bool valid = (n < NNODES);
        // ---- prologue: desc gather (g_desch from k_front, transitively done) ----
        if (valid) {
            int l = t2 >> 3, r = t2 & 7;
            int idx = node_descs[n * DESCL + l];
            uint4 u = ((const uint4*)(g_desch + (size_t)idx * GDIM))[r];
            __half2* hp = (__half2*)&u;
            float2 f0 = __half22float2(hp[0]);
            float2 f1 = __half22float2(hp[1]);
            float2 f2 = __half22float2(hp[2]);
            float2 f3 = __half22float2(hp[3]);
            float4* dp = (float4*)&ds[sub][l * DP + r * 8];
            dp[0] = make_float4(f0.x, f0.y, f1.x, f1.y);
            dp[1] = make_float4(f2.x, f2.y, f3.x, f3.y);
        }
#if __CUDA_ARCH__ >= 900
        cudaGridDependencySynchronize();   // needs g_qg from GRU
#endif
        if (tid < 256) qgs[tid] = g_qg[tid] + b_hg[tid & 63];
        __syncthreads();
        if (valid && t2 < NB * DESCL) {
            int b = t2 >> 4, l = t2 & 15;
            float s = 0.f;
#pragma unroll 8
            for (int g = 0; g < GDIM; g++) s += ds[sub][l * DP + g] * qgs[b * GDIM + g];
            sc[sub][t2] = s;
        }
        __syncthreads();
        if (valid && t2 < NB) {
            float m = -1e30f;
            for (int l = 0; l < DESCL; l++) m = fmaxf(m, sc[sub][t2 * DESCL + l]);
            float su = 0.f;
            for (int l = 0; l < DESCL; l++) { float e = __expf(sc[sub][t2 * DESCL + l] - m); at[sub][t2 * DESCL + l] = e; su += e; }
            float inv = 1.f / su;
            for (int l = 0; l < DESCL; l++) at[sub][t2 * DESCL + l] *= inv;
        }
        __syncthreads();
        if (valid) {
            int g = t2 & 63, brow = t2 >> 6;
#pragma unroll
            for (int bb = 0; bb < 2; bb++) {
                int b = brow + bb * 2;
                float o = 0.f;
#pragma unroll
                for (int l = 0; l < DESCL; l++) o += at[sub][b * DESCL + l] * ds[sub][l * DP + g];
                g_nfh[(size_t)n * 256 + b * 64 + g] = __float2half(o);
            }
        }
    }
#if __CUDA_ARCH__ >= 900
    cudaTriggerProgrammaticLaunchCompletion();
#endif
}

// =====================================================================
// Launch 4 (1250 blocks x 512): gather + transform + relu + score
// Round-11 proven gather: contiguous unroll-4, regs=40, 3 CTAs/SM.
// =====================================================================
__global__ void __launch_bounds__(512) k_gts(
    const float* __restrict__ bases, const float* __restrict__ rgcn_bias,
    const float* __restrict__ b_hg) {
    __shared__ float ar[64 * 64];        // 16 KB: rows [nl][b]
    __shared__ float B0s[GDIM * GDIM];   // 16 KB
    __shared__ float qgs[NB * GDIM];     // 1 KB
    int tid = threadIdx.x;
    int n0 = blockIdx.x * 16;
    // ---- prologue: B0 + qgs (qg transitively complete; bases is input) ----
    for (int i = tid; i < 1024; i += 512)
        ((float4*)B0s)[i] = ((const float4*)bases)[i];
    if (tid < 256) qgs[tid] = g_qg[tid] + b_hg[tid & 63];
#if __CUDA_ARCH__ >= 900
    cudaGridDependencySynchronize();     // needs nfh + CSR from k_mid
#endif

    // ---- gather: warp w = node n0+w; lane q loads uint4 #q of 512B row ----
    {
        int w = tid >> 5, q = tid & 31;
        int n = n0 + w;
        int beg = g_offsets[n], end = g_offsets[n + 1];
        float a[8];
#pragma unroll
        for (int j = 0; j < 8; j++) a[j] = 0.f;
        const uint4* nf4 = (const uint4*)g_nfh;
#define ACC8(Uv, wv) { \
        const __half2* hp_ = (const __half2*)&(Uv); \
        float2 f0_ = __half22float2(hp_[0]); float2 f1_ = __half22float2(hp_[1]); \
        float2 f2_ = __half22float2(hp_[2]); float2 f3_ = __half22float2(hp_[3]); \
        a[0] += (wv) * f0_.x; a[1] += (wv) * f0_.y; \
        a[2] += (wv) * f1_.x; a[3] += (wv) * f1_.y; \
        a[4] += (wv) * f2_.x; a[5] += (wv) * f2_.y; \
        a[6] += (wv) * f3_.x; a[7] += (wv) * f3_.y; }
        int e = beg;
        for (; e + 3 < end; e += 4) {
            int   s0 = g_ssrc[e],     s1 = g_ssrc[e + 1];
            int   s2 = g_ssrc[e + 2], s3 = g_ssrc[e + 3];
            float w0 = g_sw[e],     w1 = g_sw[e + 1];
            float w2 = g_sw[e + 2], w3 = g_sw[e + 3];
            uint4 U0 = nf4[(long)s0 * 32 + q];
            uint4 U1 = nf4[(long)s1 * 32 + q];
            uint4 U2 = nf4[(long)s2 * 32 + q];
            uint4 U3 = nf4[(long)s3 * 32 + q];
            ACC8(U0, w0); ACC8(U1, w1); ACC8(U2, w2); ACC8(U3, w3);
        }
        for (; e < end; e++) {
            int s0 = g_ssrc[e]; float w0 = g_sw[e];
            uint4 U0 = nf4[(long)s0 * 32 + q];
            ACC8(U0, w0);
        }
#undef ACC8
        int b = q >> 3, g0 = (q & 7) * 8;
        float4* pa = (float4*)&ar[(w * 4 + b) * 64 + g0];
        pa[0] = make_float4(a[0], a[1], a[2], a[3]);
        pa[1] = make_float4(a[4], a[5], a[6], a[7]);
    }
    __syncthreads();

    // ---- transform: thread (rg,jq) = rows {2rg,2rg+1} x cols 4jq ----
    int rg = tid >> 4, jq = tid & 15;       // rg 0..31, 64 rows
    int r0 = rg * 2, r1 = r0 + 1;
    float4 bias4 = ((const float4*)rgcn_bias)[jq];
    float4 accA = bias4, accB = bias4;
#pragma unroll 4
    for (int kk = 0; kk < GDIM; kk += 4) {
        float4 arA = ((float4*)ar)[r0 * 16 + (kk >> 2)];
        float4 arB = ((float4*)ar)[r1 * 16 + (kk >> 2)];
        float4 b0 = ((float4*)B0s)[(kk + 0) * 16 + jq];
        float4 b1 = ((float4*)B0s)[(kk + 1) * 16 + jq];
        float4 b2v = ((float4*)B0s)[(kk + 2) * 16 + jq];
        float4 b3 = ((float4*)B0s)[(kk + 3) * 16 + jq];
        accA.x += arA.x * b0.x + arA.y * b1.x + arA.z * b2v.x + arA.w * b3.x;
        accA.y += arA.x * b0.y + arA.y * b1.y + arA.z * b2v.y + arA.w * b3.y;
        accA.z += arA.x * b0.z + arA.y * b1.z + arA.z * b2v.z + arA.w * b3.z;
        accA.w += arA.x * b0.w + arA.y * b1.w + arA.z * b2v.w + arA.w * b3.w;
        accB.x += arB.x * b0.x + arB.y * b1.x + arB.z * b2v.x + arB.w * b3.x;
        accB.y += arB.x * b0.y + arB.y * b1.y + arB.z * b2v.y + arB.w * b3.y;
        accB.z += arB.x * b0.z + arB.y * b1.z + arB.z * b2v.z + arB.w * b3.z;
        accB.w += arB.x * b0.w + arB.y * b1.w + arB.z * b2v.w + arB.w * b3.w;
    }
    accA.x = fmaxf(accA.x, 0.f); accA.y = fmaxf(accA.y, 0.f);
    accA.z = fmaxf(accA.z, 0.f); accA.w = fmaxf(accA.w, 0.f);
    accB.x = fmaxf(accB.x, 0.f); accB.y = fmaxf(accB.y, 0.f);
    accB.z = fmaxf(accB.z, 0.f); accB.w = fmaxf(accB.w, 0.f);
    long r0g = (long)blockIdx.x * 64;
    {
        union { uint2 u; __half2 h[2]; } pA, pB;
        pA.h[0] = __floats2half2_rn(accA.x, accA.y);
        pA.h[1] = __floats2half2_rn(accA.z, accA.w);
        pB.h[0] = __floats2half2_rn(accB.x, accB.y);
        pB.h[1] = __floats2half2_rn(accB.z, accB.w);
        ((uint2*)g_nf2h)[(r0g + r0) * 16 + jq] = pA.u;
        ((uint2*)g_nf2h)[(r0g + r1) * 16 + jq] = pB.u;
    }
    int bA = r0 & 3, bB = r1 & 3;
    float4 qA = ((float4*)qgs)[bA * 16 + jq];
    float4 qB = ((float4*)qgs)[bB * 16 + jq];
    float sA = accA.x * qA.x + accA.y * qA.y + accA.z * qA.z + accA.w * qA.w;
    float sB = accB.x * qB.x + accB.y * qB.y + accB.z * qB.z + accB.w * qB.w;
#pragma unroll
    for (int o = 8; o >= 1; o >>= 1) {
        sA += __shfl_xor_sync(~0u, sA, o);
        sB += __shfl_xor_sync(~0u, sB, o);
    }
    if (jq == 0) {
        int n = n0 + (r0 >> 2);
        g_s2[bA * NNODES + n] = sA;
        g_s2[bB * NNODES + n] = sB;
    }
#if __CUDA_ARCH__ >= 900
    cudaTriggerProgrammaticLaunchCompletion();
#endif
}

// =====================================================================
// Launch 5 (148 blocks x 256): online-softmax pool + fc1 + fc2 + maint.
// P2 pooling vectorized: half2 loads (full 128B warp sectors), j-range
// split across two thread halves.
// =====================================================================
__device__ __forceinline__ void gridbar(unsigned target) {
    __syncthreads();
    if (threadIdx.x == 0) {
        __threadfence();
        unsigned old = atomicAdd((unsigned*)&g_barcnt, 1u);
        if (old == gridDim.x - 1u) {
            g_barcnt = 0;
            __threadfence();
            g_barsense = target;
        } else {
            while (g_barsense != target) {}
        }
        __threadfence();
    }
    __syncthreads();
}

__global__ void __launch_bounds__(256) k_tail(
    const float* __restrict__ W1, const float* __restrict__ b1,
    const float* __restrict__ W2, const float* __restrict__ b2,
    float* __restrict__ out) {
    __shared__ float red[256];
    __shared__ float red2[256];
    __shared__ float smx[NB], sinv[NB];
    __shared__ float prob[NB * CHUNK];
    __shared__ float fs[NB * 320];
    __shared__ float hsl[1024];
    int blk = blockIdx.x, tid = threadIdx.x;
    int b = tid >> 6, l = tid & 63;
    int n0 = blk * CHUNK;
    int n1 = n0 + CHUNK; if (n1 > NNODES) n1 = NNODES;
#if __CUDA_ARCH__ >= 900
    cudaGridDependencySynchronize();     // needs s2 + nf2h from k_gts
#endif

    // ---- P0: per-block ONLINE (max, expsum) in a single g_s2 pass ----
    float m = -1e30f, s = 0.f;
    for (int n = n0 + l; n < n1; n += 64) {
        float x = g_s2[b * NNODES + n];
        float mn = fmaxf(m, x);
        s = s * __expf(m - mn) + __expf(x - mn);
        m = mn;
    }
    red[tid] = m; red2[tid] = s; __syncthreads();
#pragma unroll
    for (int o = 32; o > 0; o >>= 1) {
        if (l < o) {
            float m2 = red[tid + o], s2 = red2[tid + o];
            float mn = fmaxf(red[tid], m2);
            red2[tid] = red2[tid] * __expf(red[tid] - mn) + s2 * __expf(m2 - mn);
            red[tid] = mn;
        }
        __syncthreads();
    }
    if (l == 0) { g_pmax[blk * NB + b] = red[tid]; g_psum[blk * NB + b] = red2[tid]; }
    if (blk == 0) g_nagg[tid] = 0.f;
    gridbar(1);

    // ---- P1: combine the 148 (m,s) pairs ----
    float M = -1e30f, S = 0.f;
    for (int i = l; i < TGRID; i += 64) {
        float m2 = g_pmax[i * NB + b], s2 = g_psum[i * NB + b];
        float mn = fmaxf(M, m2);
        S = S * __expf(M - mn) + s2 * __expf(m2 - mn);
        M = mn;
    }
    red[tid] = M; red2[tid] = S; __syncthreads();
#pragma unroll
    for (int o = 32; o > 0; o >>= 1) {
        if (l < o) {
            float m2 = red[tid + o], s2 = red2[tid + o];
            float mn = fmaxf(red[tid], m2);
            red2[tid] = red2[tid] * __expf(red[tid] - mn) + s2 * __expf(m2 - mn);
            red[tid] = mn;
        }
        __syncthreads();
    }
    if (l == 0) { smx[b] = red[tid]; sinv[b] = 1.f / red2[tid]; }
    gridbar(0);

    // ---- P2: probs; pooled weighted sum over fp16 nf2 (half2 loads) ----
    int cnt = n1 - n0;
    for (int i = tid; i < NB * CHUNK; i += 256) {
        int bb = i / CHUNK, j = i % CHUNK;
        if (j < cnt) prob[i] = __expf(g_s2[bb * NNODES + n0 + j] - smx[bb]) * sinv[bb];
    }
    __syncthreads();
    {
        int half = tid >> 7;         // j-range half 0/1
        int t2 = tid & 127;          // dim-pair index
        int d0 = t2 * 2;             // even dim; d0 and d0+1 share batch (d0/64)
        int b2 = d0 >> 6;
        float ax = 0.f, ay = 0.f;
        for (int j = half; j < cnt; j += 2) {
            float p = prob[b2 * CHUNK + j];
            __half2 v = *(const __half2*)&g_nf2h[(size_t)(n0 + j) * 256 + d0];
            float2 f = __half22float2(v);
            ax += p * f.x;
            ay += p * f.y;
        }
        atomicAdd(&g_nagg[d0],     ax);
        atomicAdd(&g_nagg[d0 + 1], ay);
    }
    gridbar(1);

    // ---- P3: fc1[0..15] | bias->out[16..47] | maintenance[48..147] ----
    if (blk < 16) {
        for (int i = tid; i < NB * 320; i += 256) {
            int bq = i / 320, kk = i % 320;
            fs[i] = (kk < 64) ? g_nagg[bq * 64 + kk] : g_qemb[bq * 256 + (kk - 64)];
        }
        __syncthreads();
        int o = blk * 256 + tid;
        int bo = o >> 10, j = o & 1023;
        float a = b1[j];
#pragma unroll 8
        for (int kk = 0; kk < 320; kk++) a += fs[bo * 320 + kk] * W1[kk * 1024 + j];
        g_hidden[o] = fmaxf(a, 0.f);
    } else if (blk < 48) {
        int idx = (blk - 16) * 256 + tid;
        if (idx < NB * NCLASS) out[idx] = b2[idx % NCLASS];
    } else {
        int idx = (blk - 48) * 256 + tid;
        if (idx < NNODES) g_counts[idx] = 0;
        else {
            int j = idx - NNODES;
            if (j < NB * GDIM) g_qg[j] = 0.f;
        }
    }
    gridbar(0);

    // ---- P4: fc2 k-split x4 over 128 blocks ----
    if (blk < 128) {
        int kc = blk >> 5, oc = blk & 31;
        for (int i = tid; i < 1024; i += 256)
            hsl[i] = g_hidden[(i >> 8) * 1024 + kc * 256 + (i & 255)];
        __syncthreads();
        int o = oc * 256 + tid;
        if (o < NB * NCLASS) {
            int bo = o / NCLASS, j = o - bo * NCLASS;
            float a = 0.f;
#pragma unroll 8
            for (int kk = 0; kk < 256; kk++)
                a += hsl[bo * 256 + kk] * W2[(kc * 256 + kk) * NCLASS + j];
            atomicAdd(&out[o], a);
        }
    }
}

// ---------------- launch -----------------------------------------------------
static inline void launch_pdl(void* fn, dim3 grid, dim3 block, void** args) {
    cudaLaunchConfig_t cfg = {};
    cfg.gridDim = grid;
    cfg.blockDim = block;
    cudaLaunchAttribute at[1];
    at[0].id = cudaLaunchAttributeProgrammaticStreamSerialization;
    at[0].val.programmaticStreamSerializationAllowed = 1;
    cfg.attrs = at;
    cfg.numAttrs = 1;
    cudaLaunchKernelExC(&cfg, fn, args);
}

extern "C" void kernel_launch(void* const* d_in, const int* in_sizes, int n_in,
                              void* d_out, int out_size) {
    const int*   questions  = (const int*)  d_in[0];
    const int*   node_descs = (const int*)  d_in[1];
    const int*   edge_src   = (const int*)  d_in[2];
    const int*   edge_dst   = (const int*)  d_in[3];
    const int*   edge_type  = (const int*)  d_in[4];
    const float* emb_word   = (const float*)d_in[5];
    const float* emb_desc   = (const float*)d_in[6];
    const float* Wx_f       = (const float*)d_in[7];
    const float* Wh_f       = (const float*)d_in[8];
    const float* bx_f       = (const float*)d_in[9];
    const float* bh_f       = (const float*)d_in[10];
    const float* Wx_b       = (const float*)d_in[11];
    const float* Wh_b       = (const float*)d_in[12];
    const float* bx_b       = (const float*)d_in[13];
    const float* bh_b       = (const float*)d_in[14];
    const float* W_hg       = (const float*)d_in[15];
    const float* b_hg       = (const float*)d_in[16];
    const float* bases      = (const float*)d_in[17];
    const float* w_comp     = (const float*)d_in[18];
    const float* rgcn_bias  = (const float*)d_in[19];
    const float* W1         = (const float*)d_in[20];
    const float* b1         = (const float*)d_in[21];
    const float* W2         = (const float*)d_in[22];
    const float* b2         = (const float*)d_in[23];
    float* out = (float*)d_out;

    k_front<<<GXB + HISTB + CONVB, 384>>>(
        questions, emb_word, Wx_f, bx_f, Wx_b, bx_b, edge_dst, emb_desc);

    {   // k_gru (PDL secondary of k_front)
        void* args[] = { (void*)&Wh_f, (void*)&bh_f, (void*)&Wh_b, (void*)&bh_b,
                         (void*)&questions, (void*)&W_hg };
        launch_pdl((void*)k_gru, dim3(9), dim3(384), args);
    }
    {   // k_mid (PDL secondary of k_gru)
        void* args[] = { (void*)&node_descs, (void*)&b_hg, (void*)&edge_src,
                         (void*)&edge_dst, (void*)&edge_type, (void*)&w_comp };
        launch_pdl((void*)k_mid, dim3(BUCKB + NFB3), dim3(384), args);
    }
    {   // k_gts (PDL secondary of k_mid)
        void* args[] = { (void*)&bases, (void*)&rgcn_bias, (void*)&b_hg };
        launch_pdl((void*)k_gts, dim3(GTSB), dim3(512), args);
    }
    {   // k_tail (PDL secondary of k_gts)
        void* args[] = { (void*)&W1, (void*)&b1, (void*)&W2, (void*)&b2, (void*)&out };
        launch_pdl((void*)k_tail, dim3(TGRID), dim3(256), args);
    }
}

// round 17
// speedup vs baseline: 1.5101x; 1.5101x over previous
#include <cuda_runtime.h>
#include <cuda_fp16.h>
#include <cuda_bf16.h>

#define NB      4
#define TT      32
#define DW      300
#define HD      128     // per-direction hidden
#define G3      384     // 3*HD
#define HID     256     // DIM_HIDDEN
#define GDIM    64
#define DESCL   16
#define NNODES  20000
#define NEDGES  320000
#define NCLASS  2000
#define VDESC   30000
#define DP      68      // padded desc row in smem
#define TGRID   148
#define CHUNK   136     // ceil(NNODES/TGRID)

// launch-1 block layout
#define GXB     64
#define HISTB   140
#define CONVB   80
#define NCONV   (VDESC * GDIM / 8)   // 240000 uint4 outputs

// launch-3 block layout
#define BUCKB   150
#define NFB3    ((NNODES + 2) / 3)   // 6667 nodefeat blocks (3 nodes each)

// launch-4: gts, 16 nodes per block, 1 warp per node (round-11 proven optimum)
#define GTSB    (NNODES / 16)        // 1250

// ---------------- scratch (device globals; zero-init at load) ---------------
// g_counts, g_qg start zero and are re-zeroed by the tail of each call.
__device__ float g_gxa[2 * NB * TT * G3];
__device__ float g_gxb[2 * NB * TT * G3];
__device__ float g_qemb[NB * HID];
__device__ float g_qg[NB * GDIM];             // accum: maintained zero
__device__ __half g_desch[(size_t)VDESC * GDIM];      // fp16 desc table
__device__ __half g_nfh[(size_t)NNODES * NB * GDIM];  // node feats (fp16)
__device__ __half g_nf2h[(size_t)NNODES * NB * GDIM]; // post-RGCN (fp16)
__device__ int   g_counts[NNODES];            // maintained zero
__device__ int   g_offsets[NNODES + 1];
__device__ int   g_cursor[NNODES];
__device__ int   g_ssrc[NEDGES];
__device__ float g_sw[NEDGES];
__device__ float g_s2[NB * NNODES];
__device__ float g_pmax[TGRID * NB];
__device__ float g_psum[TGRID * NB];
__device__ float g_nagg[NB * GDIM];
__device__ float g_hidden[NB * 1024];
__device__ volatile unsigned g_barcnt;
__device__ volatile unsigned g_barsense;

__device__ __forceinline__ float sigmoidf_(float x) { return 1.f / (1.f + __expf(-x)); }

// =====================================================================
// Launch 1 (384 thr): gx[0,64) | hist | desc->fp16   (all low-register)
// =====================================================================
__global__ void __launch_bounds__(384) k_front(
    const int* __restrict__ q, const float* __restrict__ emb_word,
    const float* __restrict__ Wx_f, const float* __restrict__ bx_f,
    const float* __restrict__ Wx_b, const float* __restrict__ bx_b,
    const int* __restrict__ edst, const float* __restrict__ emb_desc) {
    int bid = blockIdx.x, tid = threadIdx.x;
    if (bid < GXB) {
        int half = bid >> 5, dir = (bid >> 4) & 1, b = (bid >> 2) & 3, tq = bid & 3;
        const float* Wx = dir ? Wx_b : Wx_f;
        const float* bx = dir ? bx_b : bx_f;
        int k0 = half * 150;
        __shared__ float xs[8 * 150];
        for (int i = tid; i < 8 * 150; i += 384) {
            int t = i / 150, k = i % 150;
            int tok = q[b * TT + tq * 8 + t];
            xs[i] = emb_word[(long)tok * DW + k0 + k];
        }
        __syncthreads();
        float acc[8];
        float bj = half ? 0.f : bx[tid];
#pragma unroll
        for (int t = 0; t < 8; t++) acc[t] = bj;
        for (int k = 0; k < 150; k++) {
            float w = Wx[(long)(k0 + k) * G3 + tid];
#pragma unroll
            for (int t = 0; t < 8; t++) acc[t] += xs[t * 150 + k] * w;
        }
        float* dst = half ? g_gxb : g_gxa;
#pragma unroll
        for (int t = 0; t < 8; t++)
            dst[((dir * NB + b) * TT + tq * 8 + t) * G3 + tid] = acc[t];
    } else if (bid < GXB + HISTB) {
        for (int i = (bid - GXB) * 384 + tid; i < NEDGES; i += HISTB * 384)
            atomicAdd(&g_counts[edst[i]], 1);
    } else {
        const float4* src = (const float4*)emb_desc;
        for (int j = (bid - GXB - HISTB) * 384 + tid; j < NCONV; j += CONVB * 384) {
            float4 a = src[2 * j], c = src[2 * j + 1];
            union { uint4 u; __half2 h[4]; } pk;
            pk.h[0] = __float22half2_rn(make_float2(a.x, a.y));
            pk.h[1] = __float22half2_rn(make_float2(a.z, a.w));
            pk.h[2] = __float22half2_rn(make_float2(c.x, c.y));
            pk.h[3] = __float22half2_rn(make_float2(c.z, c.w));
            ((uint4*)g_desch)[j] = pk.u;
        }
    }
#if __CUDA_ARCH__ >= 900
    cudaTriggerProgrammaticLaunchCompletion();
#endif
}

// =====================================================================
// Launch 2 (9 blocks x 384): GRU[0..7] (Wh register-resident + q_g GEMV)
//                            + scan[8] (runs concurrent; its time hides)
// PDL secondary: Wh preload happens BEFORE the dependency sync.
// =====================================================================
__global__ void __launch_bounds__(384, 1) k_gru(
    const float* __restrict__ Wh_f, const float* __restrict__ bh_f,
    const float* __restrict__ Wh_b, const float* __restrict__ bh_b,
    const int* __restrict__ q, const float* __restrict__ W_hg) {
    int tid = threadIdx.x;
    if (blockIdx.x < 8) {
        __shared__ float4 h4s[HD / 4];
        __shared__ float ghs[G3];
        int rb = blockIdx.x;
        int dir = rb >> 2, b = rb & 3;
        const float* Wh = dir ? Wh_b : Wh_f;
        const float* bh = dir ? bh_b : bh_f;
        float w[HD];
#pragma unroll
        for (int k = 0; k < HD; k++) w[k] = Wh[k * G3 + tid];
        float bhj = bh[tid];
        float hreg = 0.f;
        if (tid < HD) ((float*)h4s)[tid] = 0.f;
#if __CUDA_ARCH__ >= 900
        cudaGridDependencySynchronize();   // wait for gx before recurrence
#endif
        __syncthreads();
        for (int step = 0; step < TT; step++) {
            int t = dir ? (TT - 1 - step) : step;
            const float* gA = &g_gxa[((dir * NB + b) * TT + t) * G3];
            const float* gB = &g_gxb[((dir * NB + b) * TT + t) * G3];
            float gx0 = 0.f, gx1 = 0.f, gx2 = 0.f;
            int mtok = 0;
            if (tid < HD) {
                gx0 = gA[tid] + gB[tid];
                gx1 = gA[tid + HD] + gB[tid + HD];
                gx2 = gA[tid + 2 * HD] + gB[tid + 2 * HD];
                mtok = q[b * TT + t];
            }
            float acc = bhj;
#pragma unroll
            for (int k4 = 0; k4 < HD / 4; k4++) {
                float4 h4 = h4s[k4];
                acc += h4.x * w[4 * k4] + h4.y * w[4 * k4 + 1]
                     + h4.z * w[4 * k4 + 2] + h4.w * w[4 * k4 + 3];
            }
            ghs[tid] = acc;
            __syncthreads();
            if (tid < HD) {
                float r  = sigmoidf_(gx0 + acc);
                float z  = sigmoidf_(gx1 + ghs[tid + HD]);
                float nn = tanhf(gx2 + r * ghs[tid + 2 * HD]);
                float hnew = (1.f - z) * nn + z * hreg;
                hreg = mtok ? hnew : hreg;
                ((float*)h4s)[tid] = hreg;
            }
            __syncthreads();
        }
        if (tid < HD) g_qemb[b * HID + dir * HD + tid] = hreg;
        if (tid < GDIM) {
            const float* hh = (const float*)h4s;
            float acc = 0.f;
#pragma unroll 8
            for (int k = 0; k < HD; k++)
                acc += hh[k] * W_hg[(dir * HD + k) * GDIM + tid];
            atomicAdd(&g_qg[b * GDIM + tid], acc);
        }
    } else {
        // ---- exclusive scan of g_counts -> g_offsets, g_cursor (384 thr) ----
#if __CUDA_ARCH__ >= 900
        cudaGridDependencySynchronize();   // counts must be final
#endif
        __shared__ int wsum[12];
        __shared__ int carry_s;
        int lane = tid & 31, wid = tid >> 5;
        if (tid == 0) carry_s = 0;
        __syncthreads();
        int nchunk = (NNODES + 383) / 384;
        for (int c = 0; c < nchunk; c++) {
            int i = c * 384 + tid;
            int v = (i < NNODES) ? g_counts[i] : 0;
            int x = v;
#pragma unroll
            for (int o = 1; o < 32; o <<= 1) { int y = __shfl_up_sync(~0u, x, o); if (lane >= o) x += y; }
            if (lane == 31) wsum[wid] = x;
            __syncthreads();
            if (wid == 0) {
                int s = (lane < 12) ? wsum[lane] : 0;
#pragma unroll
                for (int o = 1; o < 32; o <<= 1) { int y = __shfl_up_sync(~0u, s, o); if (lane >= o) s += y; }
                if (lane < 12) wsum[lane] = s;
            }
            __syncthreads();
            int incl = x + (wid > 0 ? wsum[wid - 1] : 0);
            int total = wsum[11];
            int base = carry_s;
            if (i < NNODES) { int e = base + incl - v; g_offsets[i] = e; g_cursor[i] = e; }
            __syncthreads();
            if (tid == 0) carry_s = base + total;
            __syncthreads();
        }
        if (tid == 0) g_offsets[NNODES] = carry_s;
    }
#if __CUDA_ARCH__ >= 900
    cudaTriggerProgrammaticLaunchCompletion();
#endif
}

// =====================================================================
// Launch 3 (384 thr): bucket[0,150) | nodefeat (3 nodes/block)
// PDL secondary: nodefeat desc gather (safe 2 launches back) precedes sync.
// =====================================================================
__global__ void __launch_bounds__(384) k_mid(
    const int* __restrict__ node_descs, const float* __restrict__ b_hg,
    const int* __restrict__ esrc, const int* __restrict__ edst,
    const int* __restrict__ etype, const float* __restrict__ w_comp) {
    int blk = blockIdx.x, tid = threadIdx.x;
    if (blk < BUCKB) {
#if __CUDA_ARCH__ >= 900
        cudaGridDependencySynchronize();   // needs g_cursor from scan
#endif
        for (int i = blk * 384 + tid; i < NEDGES; i += BUCKB * 384) {
            int d = edst[i];
            int pos = atomicAdd(&g_cursor[d], 1);
            g_ssrc[pos] = esrc[i];
            g_sw[pos]   = w_comp[etype[i]];
        }
    } else {
        __shared__ float ds[3][DESCL * DP];
        __shared__ float qgs[NB * GDIM];
        __shared__ float sc[3][NB * DESCL];
        __shared__ float at[3][NB * DESCL];
        int sub = tid >> 7, t2 = tid & 127;      // 3 nodes, 128 threads each
        int n = (blk - BUCKB) * 3 + sub;
        bool valid = (n < NNODES);
        // ---- prologue: desc gather (g_desch from k_front, transitively done) ----
        if (valid) {
            int l = t2 >> 3, r = t2 & 7;
            int idx = node_descs[n * DESCL + l];
            uint4 u = ((const uint4*)(g_desch + (size_t)idx * GDIM))[r];
            __half2* hp = (__half2*)&u;
            float2 f0 = __half22float2(hp[0]);
            float2 f1 = __half22float2(hp[1]);
            float2 f2 = __half22float2(hp[2]);
            float2 f3 = __half22float2(hp[3]);
            float4* dp = (float4*)&ds[sub][l * DP + r * 8];
            dp[0] = make_float4(f0.x, f0.y, f1.x, f1.y);
            dp[1] = make_float4(f2.x, f2.y, f3.x, f3.y);
        }
#if __CUDA_ARCH__ >= 900
        cudaGridDependencySynchronize();   // needs g_qg from GRU
#endif
        if (tid < 256) qgs[tid] = g_qg[tid] + b_hg[tid & 63];
        __syncthreads();
        if (valid && t2 < NB * DESCL) {
            int b = t2 >> 4, l = t2 & 15;
            float s = 0.f;
#pragma unroll 8
            for (int g = 0; g < GDIM; g++) s += ds[sub][l * DP + g] * qgs[b * GDIM + g];
            sc[sub][t2] = s;
        }
        __syncthreads();
        if (valid && t2 < NB) {
            float m = -1e30f;
            for (int l = 0; l < DESCL; l++) m = fmaxf(m, sc[sub][t2 * DESCL + l]);
            float su = 0.f;
            for (int l = 0; l < DESCL; l++) { float e = __expf(sc[sub][t2 * DESCL + l] - m); at[sub][t2 * DESCL + l] = e; su += e; }
            float inv = 1.f / su;
            for (int l = 0; l < DESCL; l++) at[sub][t2 * DESCL + l] *= inv;
        }
        __syncthreads();
        if (valid) {
            int g = t2 & 63, brow = t2 >> 6;
#pragma unroll
            for (int bb = 0; bb < 2; bb++) {
                int b = brow + bb * 2;
                float o = 0.f;
#pragma unroll
                for (int l = 0; l < DESCL; l++) o += at[sub][b * DESCL + l] * ds[sub][l * DP + g];
                g_nfh[(size_t)n * 256 + b * 64 + g] = __float2half(o);
            }
        }
    }
#if __CUDA_ARCH__ >= 900
    cudaTriggerProgrammaticLaunchCompletion();
#endif
}

// =====================================================================
// Launch 4 (1250 blocks x 512): gather + transform + relu + score
// Round-11 proven gather: contiguous unroll-4, regs=40, 3 CTAs/SM.
// =====================================================================
__global__ void __launch_bounds__(512) k_gts(
    const float* __restrict__ bases, const float* __restrict__ rgcn_bias,
    const float* __restrict__ b_hg) {
    __shared__ float ar[64 * 64];        // 16 KB: rows [nl][b]
    __shared__ float B0s[GDIM * GDIM];   // 16 KB
    __shared__ float qgs[NB * GDIM];     // 1 KB
    int tid = threadIdx.x;
    int n0 = blockIdx.x * 16;
    // ---- prologue: B0 + qgs (qg transitively complete; bases is input) ----
    for (int i = tid; i < 1024; i += 512)
        ((float4*)B0s)[i] = ((const float4*)bases)[i];
    if (tid < 256) qgs[tid] = g_qg[tid] + b_hg[tid & 63];
#if __CUDA_ARCH__ >= 900
    cudaGridDependencySynchronize();     // needs nfh + CSR from k_mid
#endif

    // ---- gather: warp w = node n0+w; lane q loads uint4 #q of 512B row ----
    {
        int w = tid >> 5, q = tid & 31;
        int n = n0 + w;
        int beg = g_offsets[n], end = g_offsets[n + 1];
        float a[8];
#pragma unroll
        for (int j = 0; j < 8; j++) a[j] = 0.f;
        const uint4* nf4 = (const uint4*)g_nfh;
#define ACC8(Uv, wv) { \
        const __half2* hp_ = (const __half2*)&(Uv); \
        float2 f0_ = __half22float2(hp_[0]); float2 f1_ = __half22float2(hp_[1]); \
        float2 f2_ = __half22float2(hp_[2]); float2 f3_ = __half22float2(hp_[3]); \
        a[0] += (wv) * f0_.x; a[1] += (wv) * f0_.y; \
        a[2] += (wv) * f1_.x; a[3] += (wv) * f1_.y; \
        a[4] += (wv) * f2_.x; a[5] += (wv) * f2_.y; \
        a[6] += (wv) * f3_.x; a[7] += (wv) * f3_.y; }
        int e = beg;
        for (; e + 3 < end; e += 4) {
            int   s0 = g_ssrc[e],     s1 = g_ssrc[e + 1];
            int   s2 = g_ssrc[e + 2], s3 = g_ssrc[e + 3];
            float w0 = g_sw[e],     w1 = g_sw[e + 1];
            float w2 = g_sw[e + 2], w3 = g_sw[e + 3];
            uint4 U0 = nf4[(long)s0 * 32 + q];
            uint4 U1 = nf4[(long)s1 * 32 + q];
            uint4 U2 = nf4[(long)s2 * 32 + q];
            uint4 U3 = nf4[(long)s3 * 32 + q];
            ACC8(U0, w0); ACC8(U1, w1); ACC8(U2, w2); ACC8(U3, w3);
        }
        for (; e < end; e++) {
            int s0 = g_ssrc[e]; float w0 = g_sw[e];
            uint4 U0 = nf4[(long)s0 * 32 + q];
            ACC8(U0, w0);
        }
#undef ACC8
        int b = q >> 3, g0 = (q & 7) * 8;
        float4* pa = (float4*)&ar[(w * 4 + b) * 64 + g0];
        pa[0] = make_float4(a[0], a[1], a[2], a[3]);
        pa[1] = make_float4(a[4], a[5], a[6], a[7]);
    }
    __syncthreads();

    // ---- transform: thread (rg,jq) = rows {2rg,2rg+1} x cols 4jq ----
    int rg = tid >> 4, jq = tid & 15;       // rg 0..31, 64 rows
    int r0 = rg * 2, r1 = r0 + 1;
    float4 bias4 = ((const float4*)rgcn_bias)[jq];
    float4 accA = bias4, accB = bias4;
#pragma unroll 4
    for (int kk = 0; kk < GDIM; kk += 4) {
        float4 arA = ((float4*)ar)[r0 * 16 + (kk >> 2)];
        float4 arB = ((float4*)ar)[r1 * 16 + (kk >> 2)];
        float4 b0 = ((float4*)B0s)[(kk + 0) * 16 + jq];
        float4 b1 = ((float4*)B0s)[(kk + 1) * 16 + jq];
        float4 b2v = ((float4*)B0s)[(kk + 2) * 16 + jq];
        float4 b3 = ((float4*)B0s)[(kk + 3) * 16 + jq];
        accA.x += arA.x * b0.x + arA.y * b1.x + arA.z * b2v.x + arA.w * b3.x;
        accA.y += arA.x * b0.y + arA.y * b1.y + arA.z * b2v.y + arA.w * b3.y;
        accA.z += arA.x * b0.z + arA.y * b1.z + arA.z * b2v.z + arA.w * b3.z;
        accA.w += arA.x * b0.w + arA.y * b1.w + arA.z * b2v.w + arA.w * b3.w;
        accB.x += arB.x * b0.x + arB.y * b1.x + arB.z * b2v.x + arB.w * b3.x;
        accB.y += arB.x * b0.y + arB.y * b1.y + arB.z * b2v.y + arB.w * b3.y;
        accB.z += arB.x * b0.z + arB.y * b1.z + arB.z * b2v.z + arB.w * b3.z;
        accB.w += arB.x * b0.w + arB.y * b1.w + arB.z * b2v.w + arB.w * b3.w;
    }
    accA.x = fmaxf(accA.x, 0.f); accA.y = fmaxf(accA.y, 0.f);
    accA.z = fmaxf(accA.z, 0.f); accA.w = fmaxf(accA.w, 0.f);
    accB.x = fmaxf(accB.x, 0.f); accB.y = fmaxf(accB.y, 0.f);
    accB.z = fmaxf(accB.z, 0.f); accB.w = fmaxf(accB.w, 0.f);
    long r0g = (long)blockIdx.x * 64;
    {
        union { uint2 u; __half2 h[2]; } pA, pB;
        pA.h[0] = __floats2half2_rn(accA.x, accA.y);
        pA.h[1] = __floats2half2_rn(accA.z, accA.w);
        pB.h[0] = __floats2half2_rn(accB.x, accB.y);
        pB.h[1] = __floats2half2_rn(accB.z, accB.w);
        ((uint2*)g_nf2h)[(r0g + r0) * 16 + jq] = pA.u;
        ((uint2*)g_nf2h)[(r0g + r1) * 16 + jq] = pB.u;
    }
    int bA = r0 & 3, bB = r1 & 3;
    float4 qA = ((float4*)qgs)[bA * 16 + jq];
    float4 qB = ((float4*)qgs)[bB * 16 + jq];
    float sA = accA.x * qA.x + accA.y * qA.y + accA.z * qA.z + accA.w * qA.w;
    float sB = accB.x * qB.x + accB.y * qB.y + accB.z * qB.z + accB.w * qB.w;
#pragma unroll
    for (int o = 8; o >= 1; o >>= 1) {
        sA += __shfl_xor_sync(~0u, sA, o);
        sB += __shfl_xor_sync(~0u, sB, o);
    }
    if (jq == 0) {
        int n = n0 + (r0 >> 2);
        g_s2[bA * NNODES + n] = sA;
        g_s2[bB * NNODES + n] = sB;
    }
#if __CUDA_ARCH__ >= 900
    cudaTriggerProgrammaticLaunchCompletion();
#endif
}

// =====================================================================
// Launch 5 (148 blocks x 256): online-softmax pool + fc1 + fc2 + maint.
// P2 pooling vectorized: half2 loads (full 128B warp sectors), j-range
// split across two thread halves.
// =====================================================================
__device__ __forceinline__ void gridbar(unsigned target) {
    __syncthreads();
    if (threadIdx.x == 0) {
        __threadfence();
        unsigned old = atomicAdd((unsigned*)&g_barcnt, 1u);
        if (old == gridDim.x - 1u) {
            g_barcnt = 0;
            __threadfence();
            g_barsense = target;
        } else {
            while (g_barsense != target) {}
        }
        __threadfence();
    }
    __syncthreads();
}

__global__ void __launch_bounds__(256) k_tail(
    const float* __restrict__ W1, const float* __restrict__ b1,
    const float* __restrict__ W2, const float* __restrict__ b2,
    float* __restrict__ out) {
    __shared__ float red[256];
    __shared__ float red2[256];
    __shared__ float smx[NB], sinv[NB];
    __shared__ float prob[NB * CHUNK];
    __shared__ float fs[NB * 320];
    __shared__ float hsl[1024];
    int blk = blockIdx.x, tid = threadIdx.x;
    int b = tid >> 6, l = tid & 63;
    int n0 = blk * CHUNK;
    int n1 = n0 + CHUNK; if (n1 > NNODES) n1 = NNODES;
#if __CUDA_ARCH__ >= 900
    cudaGridDependencySynchronize();     // needs s2 + nf2h from k_gts
#endif

    // ---- P0: per-block ONLINE (max, expsum) in a single g_s2 pass ----
    float m = -1e30f, s = 0.f;
    for (int n = n0 + l; n < n1; n += 64) {
        float x = g_s2[b * NNODES + n];
        float mn = fmaxf(m, x);
        s = s * __expf(m - mn) + __expf(x - mn);
        m = mn;
    }
    red[tid] = m; red2[tid] = s; __syncthreads();
#pragma unroll
    for (int o = 32; o > 0; o >>= 1) {
        if (l < o) {
            float m2 = red[tid + o], s2 = red2[tid + o];
            float mn = fmaxf(red[tid], m2);
            red2[tid] = red2[tid] * __expf(red[tid] - mn) + s2 * __expf(m2 - mn);
            red[tid] = mn;
        }
        __syncthreads();
    }
    if (l == 0) { g_pmax[blk * NB + b] = red[tid]; g_psum[blk * NB + b] = red2[tid]; }
    if (blk == 0) g_nagg[tid] = 0.f;
    gridbar(1);

    // ---- P1: combine the 148 (m,s) pairs ----
    float M = -1e30f, S = 0.f;
    for (int i = l; i < TGRID; i += 64) {
        float m2 = g_pmax[i * NB + b], s2 = g_psum[i * NB + b];
        float mn = fmaxf(M, m2);
        S = S * __expf(M - mn) + s2 * __expf(m2 - mn);
        M = mn;
    }
    red[tid] = M; red2[tid] = S; __syncthreads();
#pragma unroll
    for (int o = 32; o > 0; o >>= 1) {
        if (l < o) {
            float m2 = red[tid + o], s2 = red2[tid + o];
            float mn = fmaxf(red[tid], m2);
            red2[tid] = red2[tid] * __expf(red[tid] - mn) + s2 * __expf(m2 - mn);
            red[tid] = mn;
        }
        __syncthreads();
    }
    if (l == 0) { smx[b] = red[tid]; sinv[b] = 1.f / red2[tid]; }
    gridbar(0);

    // ---- P2: probs; pooled weighted sum over fp16 nf2 (half2 loads) ----
    int cnt = n1 - n0;
    for (int i = tid; i < NB * CHUNK; i += 256) {
        int bb = i / CHUNK, j = i % CHUNK;
        if (j < cnt) prob[i] = __expf(g_s2[bb * NNODES + n0 + j] - smx[bb]) * sinv[bb];
    }
    __syncthreads();
    {
        int half = tid >> 7;         // j-range half 0/1
        int t2 = tid & 127;          // dim-pair index
        int d0 = t2 * 2;             // even dim; d0 and d0+1 share batch (d0/64)
        int b2 = d0 >> 6;
        float ax = 0.f, ay = 0.f;
        for (int j = half; j < cnt; j += 2) {
            float p = prob[b2 * CHUNK + j];
            __half2 v = *(const __half2*)&g_nf2h[(size_t)(n0 + j) * 256 + d0];
            float2 f = __half22float2(v);
            ax += p * f.x;
            ay += p * f.y;
        }
        atomicAdd(&g_nagg[d0],     ax);
        atomicAdd(&g_nagg[d0 + 1], ay);
    }
    gridbar(1);

    // ---- P3: fc1[0..15] | bias->out[16..47] | maintenance[48..147] ----
    if (blk < 16) {
        for (int i = tid; i < NB * 320; i += 256) {
            int bq = i / 320, kk = i % 320;
            fs[i] = (kk < 64) ? g_nagg[bq * 64 + kk] : g_qemb[bq * 256 + (kk - 64)];
        }
        __syncthreads();
        int o = blk * 256 + tid;
        int bo = o >> 10, j = o & 1023;
        float a = b1[j];
#pragma unroll 8
        for (int kk = 0; kk < 320; kk++) a += fs[bo * 320 + kk] * W1[kk * 1024 + j];
        g_hidden[o] = fmaxf(a, 0.f);
    } else if (blk < 48) {
        int idx = (blk - 16) * 256 + tid;
        if (idx < NB * NCLASS) out[idx] = b2[idx % NCLASS];
    } else {
        int idx = (blk - 48) * 256 + tid;
        if (idx < NNODES) g_counts[idx] = 0;
        else {
            int j = idx - NNODES;
            if (j < NB * GDIM) g_qg[j] = 0.f;
        }
    }
    gridbar(0);

    // ---- P4: fc2 k-split x4 over 128 blocks ----
    if (blk < 128) {
        int kc = blk >> 5, oc = blk & 31;
        for (int i = tid; i < 1024; i += 256)
            hsl[i] = g_hidden[(i >> 8) * 1024 + kc * 256 + (i & 255)];
        __syncthreads();
        int o = oc * 256 + tid;
        if (o < NB * NCLASS) {
            int bo = o / NCLASS, j = o - bo * NCLASS;
            float a = 0.f;
#pragma unroll 8
            for (int kk = 0; kk < 256; kk++)
                a += hsl[bo * 256 + kk] * W2[(kc * 256 + kk) * NCLASS + j];
            atomicAdd(&out[o], a);
        }
    }
}

// ---------------- launch -----------------------------------------------------
static inline void launch_pdl(void* fn, dim3 grid, dim3 block, void** args) {
    cudaLaunchConfig_t cfg = {};
    cfg.gridDim = grid;
    cfg.blockDim = block;
    cudaLaunchAttribute at[1];
    at[0].id = cudaLaunchAttributeProgrammaticStreamSerialization;
    at[0].val.programmaticStreamSerializationAllowed = 1;
    cfg.attrs = at;
    cfg.numAttrs = 1;
    cudaLaunchKernelExC(&cfg, fn, args);
}

extern "C" void kernel_launch(void* const* d_in, const int* in_sizes, int n_in,
                              void* d_out, int out_size) {
    const int*   questions  = (const int*)  d_in[0];
    const int*   node_descs = (const int*)  d_in[1];
    const int*   edge_src   = (const int*)  d_in[2];
    const int*   edge_dst   = (const int*)  d_in[3];
    const int*   edge_type  = (const int*)  d_in[4];
    const float* emb_word   = (const float*)d_in[5];
    const float* emb_desc   = (const float*)d_in[6];
    const float* Wx_f       = (const float*)d_in[7];
    const float* Wh_f       = (const float*)d_in[8];
    const float* bx_f       = (const float*)d_in[9];
    const float* bh_f       = (const float*)d_in[10];
    const float* Wx_b       = (const float*)d_in[11];
    const float* Wh_b       = (const float*)d_in[12];
    const float* bx_b       = (const float*)d_in[13];
    const float* bh_b       = (const float*)d_in[14];
    const float* W_hg       = (const float*)d_in[15];
    const float* b_hg       = (const float*)d_in[16];
    const float* bases      = (const float*)d_in[17];
    const float* w_comp     = (const float*)d_in[18];
    const float* rgcn_bias  = (const float*)d_in[19];
    const float* W1         = (const float*)d_in[20];
    const float* b1         = (const float*)d_in[21];
    const float* W2         = (const float*)d_in[22];
    const float* b2         = (const float*)d_in[23];
    float* out = (float*)d_out;

    k_front<<<GXB + HISTB + CONVB, 384>>>(
        questions, emb_word, Wx_f, bx_f, Wx_b, bx_b, edge_dst, emb_desc);

    {   // k_gru (PDL secondary of k_front)
        void* args[] = { (void*)&Wh_f, (void*)&bh_f, (void*)&Wh_b, (void*)&bh_b,
                         (void*)&questions, (void*)&W_hg };
        launch_pdl((void*)k_gru, dim3(9), dim3(384), args);
    }
    {   // k_mid (PDL secondary of k_gru)
        void* args[] = { (void*)&node_descs, (void*)&b_hg, (void*)&edge_src,
                         (void*)&edge_dst, (void*)&edge_type, (void*)&w_comp };
        launch_pdl((void*)k_mid, dim3(BUCKB + NFB3), dim3(384), args);
    }
    {   // k_gts (PDL secondary of k_mid)
        void* args[] = { (void*)&bases, (void*)&rgcn_bias, (void*)&b_hg };
        launch_pdl((void*)k_gts, dim3(GTSB), dim3(512), args);
    }
    {   // k_tail (PDL secondary of k_gts)
        void* args[] = { (void*)&W1, (void*)&b1, (void*)&W2, (void*)&b2, (void*)&out };
        launch_pdl((void*)k_tail, dim3(TGRID), dim3(256), args);
    }
}